// round 2
// baseline (speedup 1.0000x reference)
#include <cuda_runtime.h>
#include <cuda_bf16.h>

// ---------------------------------------------------------------------------
// 10-qubit state-vector simulator, one warp per batch element.
// State: 1024 complex amps = 32 per lane, held entirely in registers.
// Amplitude index k (10 bits): bits[9:5] = lane, bits[4:0] = register slot r.
// Qubit w <-> bit (9-w) of k  (matches reference reshape & Z_SIGNS).
// ---------------------------------------------------------------------------

#define NQ 10
#define NL 6
#define BATCH 16384
#define EMB 64

__device__ float g_gates[NL * NQ * 8];  // per gate: u00r,u00i,u01r,u01i,u10r,u10i,u11r,u11i

// ---- prep kernel: build the 60 batch-independent Rot matrices -------------
__global__ void prep_gates_kernel(const float* __restrict__ weights) {
    int i = threadIdx.x;
    if (i < NL * NQ) {
        float phi = weights[i * 3 + 0];
        float th  = weights[i * 3 + 1];
        float om  = weights[i * 3 + 2];
        float c, s;
        sincosf(0.5f * th, &s, &c);
        float a = 0.5f * (phi + om);
        float d = 0.5f * (phi - om);
        float sa, ca, sd, cd;
        sincosf(a, &sa, &ca);
        sincosf(d, &sd, &cd);
        float* g = g_gates + i * 8;
        // u00 = e^{-ia} c ; u01 = -e^{+id} s ; u10 = e^{-id} s ; u11 = e^{+ia} c
        g[0] =  ca * c;  g[1] = -sa * c;
        g[2] = -cd * s;  g[3] = -sd * s;
        g[4] =  cd * s;  g[5] = -sd * s;
        g[6] =  ca * c;  g[7] =  sa * c;
    }
}

__device__ __forceinline__ float shx(float v, int m) {
    return __shfl_xor_sync(0xffffffffu, v, m);
}

// ---- single-qubit gate on qubit W -----------------------------------------
template <int W>
__device__ __forceinline__ void apply_gate_u(
    float* ar, float* ai, int lane,
    float u00r, float u00i, float u01r, float u01i,
    float u10r, float u10i, float u11r, float u11i)
{
    constexpr int BIT = 9 - W;
    if constexpr (BIT >= 5) {
        // lane-bit gate: partner across lanes
        constexpr int ML = 1 << (BIT - 5);
        const bool hi = (lane & ML) != 0;
        const float cmr = hi ? u11r : u00r, cmi = hi ? u11i : u00i;
        const float cpr = hi ? u10r : u01r, cpi = hi ? u10i : u01i;
#pragma unroll
        for (int r = 0; r < 32; r++) {
            float pr = shx(ar[r], ML);
            float pi = shx(ai[r], ML);
            float mr = ar[r], mi = ai[r];
            ar[r] = cmr * mr - cmi * mi + cpr * pr - cpi * pi;
            ai[r] = cmr * mi + cmi * mr + cpr * pi + cpi * pr;
        }
    } else {
        // register-bit gate: pairs within this lane
        constexpr int M = 1 << BIT;
#pragma unroll
        for (int r = 0; r < 32; r++) {
            if ((r & M) == 0) {
                const int r1 = r | M;
                float a0r = ar[r],  a0i = ai[r];
                float a1r = ar[r1], a1i = ai[r1];
                ar[r]  = u00r * a0r - u00i * a0i + u01r * a1r - u01i * a1i;
                ai[r]  = u00r * a0i + u00i * a0r + u01r * a1i + u01i * a1r;
                ar[r1] = u10r * a0r - u10i * a0i + u11r * a1r - u11i * a1i;
                ai[r1] = u10r * a0i + u10i * a0r + u11r * a1i + u11i * a1r;
            }
        }
    }
}

// ---- CNOT(C, T): new[k] = old[k ^ (bit_C(k) ? mask_T : 0)] ----------------
template <int C, int T>
__device__ __forceinline__ void cnot_g(float* ar, float* ai, int lane) {
    constexpr int BC = 9 - C, BT = 9 - T;
    if constexpr (BC < 5 && BT < 5) {
        // both register bits: unconditional register swaps
        constexpr int MC = 1 << BC, MT = 1 << BT;
#pragma unroll
        for (int r = 0; r < 32; r++) {
            if ((r & MC) && !(r & MT)) {
                const int r1 = r | MT;
                float t;
                t = ar[r]; ar[r] = ar[r1]; ar[r1] = t;
                t = ai[r]; ai[r] = ai[r1]; ai[r1] = t;
            }
        }
    } else if constexpr (BC < 5 && BT >= 5) {
        // control in registers, target across lanes: exchange where ctrl=1
        constexpr int MC = 1 << BC, ML = 1 << (BT - 5);
#pragma unroll
        for (int r = 0; r < 32; r++) {
            if (r & MC) {
                ar[r] = shx(ar[r], ML);
                ai[r] = shx(ai[r], ML);
            }
        }
    } else if constexpr (BC >= 5 && BT < 5) {
        // control on lane bit, target in registers: predicated swap
        constexpr int MCL = 1 << (BC - 5), MT = 1 << BT;
        const bool ctrl = (lane & MCL) != 0;
#pragma unroll
        for (int r = 0; r < 32; r++) {
            if (!(r & MT)) {
                const int r1 = r | MT;
                float a0 = ar[r], a1 = ar[r1];
                ar[r]  = ctrl ? a1 : a0;
                ar[r1] = ctrl ? a0 : a1;
                float b0 = ai[r], b1 = ai[r1];
                ai[r]  = ctrl ? b1 : b0;
                ai[r1] = ctrl ? b0 : b1;
            }
        }
    } else {
        // both lane bits: gather from computed source lane
        constexpr int MCL = 1 << (BC - 5), MTL = 1 << (BT - 5);
        const int src = lane ^ ((lane & MCL) ? MTL : 0);
#pragma unroll
        for (int r = 0; r < 32; r++) {
            ar[r] = __shfl_sync(0xffffffffu, ar[r], src);
            ai[r] = __shfl_sync(0xffffffffu, ai[r], src);
        }
    }
}

// ---- compile-time circuit structure ---------------------------------------
template <int L, int W>
__device__ __forceinline__ void layer_rots(float* ar, float* ai, int lane,
                                           const float* __restrict__ sg) {
    if constexpr (W < NQ) {
        const float* u = sg + (L * NQ + W) * 8;
        apply_gate_u<W>(ar, ai, lane, u[0], u[1], u[2], u[3], u[4], u[5], u[6], u[7]);
        layer_rots<L, W + 1>(ar, ai, lane, sg);
    }
}

template <int L, int W>
__device__ __forceinline__ void layer_cnots(float* ar, float* ai, int lane) {
    if constexpr (W < NQ) {
        cnot_g<W, (W + (L % (NQ - 1)) + 1) % NQ>(ar, ai, lane);
        layer_cnots<L, W + 1>(ar, ai, lane);
    }
}

template <int L>
__device__ __forceinline__ void run_layers(float* ar, float* ai, int lane,
                                           const float* __restrict__ sg) {
    if constexpr (L < NL) {
        layer_rots<L, 0>(ar, ai, lane, sg);
        layer_cnots<L, 0>(ar, ai, lane);
        run_layers<L + 1>(ar, ai, lane, sg);
    }
}

template <int W>
__device__ __forceinline__ void init_rx(float* ar, float* ai, int lane,
                                        const float* halfang) {
    if constexpr (W < NQ) {
        float s, c;
        __sincosf(halfang[W], &s, &c);
        // RX: [[c, -is], [-is, c]]
        apply_gate_u<W>(ar, ai, lane, c, 0.f, 0.f, -s, 0.f, -s, c, 0.f);
        init_rx<W + 1>(ar, ai, lane, halfang);
    }
}

// ---- main kernel: 8 warps per block, 1 element per warp -------------------
__global__ void __launch_bounds__(256)
qsim_kernel(const float* __restrict__ x, const float* __restrict__ Wm,
            const float* __restrict__ b, float* __restrict__ out) {
    __shared__ float sW[NQ * EMB];
    __shared__ float sb[16];
    __shared__ float sg[NL * NQ * 8];

    const int tid = threadIdx.x;
    for (int i = tid; i < NQ * EMB; i += 256) sW[i] = Wm[i];
    if (tid < NQ) sb[tid] = b[tid];
    for (int i = tid; i < NL * NQ * 8; i += 256) sg[i] = g_gates[i];
    __syncthreads();

    const int lane = tid & 31;
    const int e = blockIdx.x * 8 + (tid >> 5);

    // angles = x[e] @ W.T + b  (half-angles)
    const float xa = x[e * EMB + lane];
    const float xb = x[e * EMB + 32 + lane];
    float halfang[NQ];
#pragma unroll
    for (int w = 0; w < NQ; w++) {
        float p = xa * sW[w * EMB + lane] + xb * sW[w * EMB + 32 + lane];
#pragma unroll
        for (int m = 16; m >= 1; m >>= 1) p += shx(p, m);
        halfang[w] = 0.5f * (p + sb[w]);
    }

    // |0...0>
    float ar[32], ai[32];
#pragma unroll
    for (int r = 0; r < 32; r++) { ar[r] = 0.f; ai[r] = 0.f; }
    if (lane == 0) ar[0] = 1.0f;

    // embedding RX gates, then 6 entangling layers
    init_rx<0>(ar, ai, lane, halfang);
    run_layers<0>(ar, ai, lane, sg);

    // readout: <Z_q> = sum_k sign_q(k) * |amp_k|^2
    float tot = 0.f, d0 = 0.f, d1 = 0.f, d2 = 0.f, d3 = 0.f, d4 = 0.f;
#pragma unroll
    for (int r = 0; r < 32; r++) {
        float p = ar[r] * ar[r] + ai[r] * ai[r];
        tot += p;
        d0 += (r & 1)  ? -p : p;
        d1 += (r & 2)  ? -p : p;
        d2 += (r & 4)  ? -p : p;
        d3 += (r & 8)  ? -p : p;
        d4 += (r & 16) ? -p : p;
    }
    float res[NQ];
    // qubits 0..4 live on lane bits 4..0
    res[0] = (lane & 16) ? -tot : tot;
    res[1] = (lane & 8)  ? -tot : tot;
    res[2] = (lane & 4)  ? -tot : tot;
    res[3] = (lane & 2)  ? -tot : tot;
    res[4] = (lane & 1)  ? -tot : tot;
    // qubits 5..9 live on register bits 4..0
    res[5] = d4; res[6] = d3; res[7] = d2; res[8] = d1; res[9] = d0;
#pragma unroll
    for (int q = 0; q < NQ; q++) {
#pragma unroll
        for (int m = 16; m >= 1; m >>= 1) res[q] += shx(res[q], m);
    }
#pragma unroll
    for (int q = 0; q < NQ; q++) {
        if (lane == q) out[e * NQ + q] = res[q];
    }
}

extern "C" void kernel_launch(void* const* d_in, const int* in_sizes, int n_in,
                              void* d_out, int out_size) {
    const float* x       = (const float*)d_in[0];  // (16384, 64)
    const float* Wm      = (const float*)d_in[1];  // (10, 64)
    const float* b       = (const float*)d_in[2];  // (10,)
    const float* weights = (const float*)d_in[3];  // (6, 10, 3)
    float* out = (float*)d_out;                    // (16384, 10)

    prep_gates_kernel<<<1, 64>>>(weights);
    qsim_kernel<<<BATCH / 8, 256>>>(x, Wm, b, out);
}

// round 3
// speedup vs baseline: 1.2019x; 1.2019x over previous
#include <cuda_runtime.h>
#include <cuda_bf16.h>

// ---------------------------------------------------------------------------
// 10-qubit state-vector simulator, one warp per batch element, f32x2 packed.
// Amplitude index k (10 bits): bits[9:5]=lane, bits[4:1]=j (reg slot),
// bit[0]=half of a packed 64-bit f32x2 value. Qubit w <-> bit (9-w).
//   qubits 0..4  -> lane bits 4..0
//   qubits 5..8  -> j bits 3..0
//   qubit  9     -> packed half (lo=0, hi=1)
// All gate math uses fma.rn.f32x2 (2 fp32 FMA per FMA-pipe issue).
// ---------------------------------------------------------------------------

#define NQ 10
#define NL 6
#define BATCH 16384
#define EMB 64

typedef unsigned long long ull;

__device__ __forceinline__ ull pack2(float lo, float hi) {
    ull r; asm("mov.b64 %0, {%1,%2};" : "=l"(r) : "f"(lo), "f"(hi)); return r;
}
__device__ __forceinline__ void unpack2(ull v, float& lo, float& hi) {
    asm("mov.b64 {%0,%1}, %2;" : "=f"(lo), "=f"(hi) : "l"(v));
}
__device__ __forceinline__ ull splat2(float x) { return pack2(x, x); }
__device__ __forceinline__ ull fma2(ull a, ull b, ull c) {
    ull d; asm("fma.rn.f32x2 %0, %1, %2, %3;" : "=l"(d) : "l"(a), "l"(b), "l"(c)); return d;
}
__device__ __forceinline__ ull mul2(ull a, ull b) {
    ull d; asm("mul.rn.f32x2 %0, %1, %2;" : "=l"(d) : "l"(a), "l"(b)); return d;
}
__device__ __forceinline__ ull swap64(ull v) {
    float lo, hi; unpack2(v, lo, hi); return pack2(hi, lo);
}
__device__ __forceinline__ ull shx64(ull v, int m) {
    float lo, hi; unpack2(v, lo, hi);
    lo = __shfl_xor_sync(0xffffffffu, lo, m);
    hi = __shfl_xor_sync(0xffffffffu, hi, m);
    return pack2(lo, hi);
}
__device__ __forceinline__ ull shidx64(ull v, int s) {
    float lo, hi; unpack2(v, lo, hi);
    lo = __shfl_sync(0xffffffffu, lo, s);
    hi = __shfl_sync(0xffffffffu, hi, s);
    return pack2(lo, hi);
}
__device__ __forceinline__ float shxf(float v, int m) {
    return __shfl_xor_sync(0xffffffffu, v, m);
}

// ---- generic Rot gate on qubit W ------------------------------------------
template <int W>
__device__ __forceinline__ void rot_gate(ull* vr, ull* vi, int lane,
                                         const float* __restrict__ u) {
    const float u00r = u[0], u00i = u[1], u01r = u[2], u01i = u[3];
    const float u10r = u[4], u10i = u[5], u11r = u[6], u11i = u[7];
    constexpr int BIT = 9 - W;
    if constexpr (BIT >= 5) {
        // lane-bit gate: partner across lanes, lane-conditional splat coeffs
        constexpr int ML = 1 << (BIT - 5);
        const bool hi = (lane & ML) != 0;
        const ull CMR  = splat2(hi ?  u11r :  u00r);
        const ull CMI  = splat2(hi ?  u11i :  u00i);
        const ull NCMI = splat2(hi ? -u11i : -u00i);
        const ull CPR  = splat2(hi ?  u10r :  u01r);
        const ull CPI  = splat2(hi ?  u10i :  u01i);
        const ull NCPI = splat2(hi ? -u10i : -u01i);
#pragma unroll
        for (int j = 0; j < 16; j++) {
            ull pr = shx64(vr[j], ML), pi = shx64(vi[j], ML);
            ull mr = vr[j], mi = vi[j];
            vr[j] = fma2(CMR, mr, fma2(NCMI, mi, fma2(CPR, pr, mul2(NCPI, pi))));
            vi[j] = fma2(CMR, mi, fma2(CMI, mr, fma2(CPR, pi, mul2(CPI, pr))));
        }
    } else if constexpr (BIT >= 1) {
        // j-bit gate: pairs of packed regs, uniform splat coeffs
        constexpr int MJ = 1 << (BIT - 1);
        const ull U00R = splat2(u00r), U00I = splat2(u00i), N00I = splat2(-u00i);
        const ull U01R = splat2(u01r), U01I = splat2(u01i), N01I = splat2(-u01i);
        const ull U10R = splat2(u10r), U10I = splat2(u10i), N10I = splat2(-u10i);
        const ull U11R = splat2(u11r), U11I = splat2(u11i), N11I = splat2(-u11i);
#pragma unroll
        for (int j = 0; j < 16; j++) {
            if (!(j & MJ)) {
                const int j1 = j | MJ;
                ull x0r = vr[j], x0i = vi[j], x1r = vr[j1], x1i = vi[j1];
                vr[j]  = fma2(U00R, x0r, fma2(N00I, x0i, fma2(U01R, x1r, mul2(N01I, x1i))));
                vi[j]  = fma2(U00R, x0i, fma2(U00I, x0r, fma2(U01R, x1i, mul2(U01I, x1r))));
                vr[j1] = fma2(U10R, x0r, fma2(N10I, x0i, fma2(U11R, x1r, mul2(N11I, x1i))));
                vi[j1] = fma2(U10R, x0i, fma2(U10I, x0r, fma2(U11R, x1i, mul2(U11I, x1r))));
            }
        }
    } else {
        // half-bit gate (qubit 9): intra-pair, needs swapped packs
        const ull P1 = pack2(u00r, u11r), P2 = pack2(u01r, u10r);
        const ull P3 = pack2(-u00i, -u11i), P4 = pack2(-u01i, -u10i);
        const ull Q3 = pack2(u00i, u11i), Q4 = pack2(u01i, u10i);
#pragma unroll
        for (int j = 0; j < 16; j++) {
            ull xr = vr[j], xi = vi[j];
            ull xrs = swap64(xr), xis = swap64(xi);
            vr[j] = fma2(P1, xr, fma2(P2, xrs, fma2(P3, xi, mul2(P4, xis))));
            vi[j] = fma2(P1, xi, fma2(P2, xis, fma2(Q3, xr, mul2(Q4, xrs))));
        }
    }
}

// ---- RX gate (embedding): U = [[c, -is], [-is, c]] ------------------------
template <int W>
__device__ __forceinline__ void rx_gate(ull* vr, ull* vi, int lane,
                                        float c, float s) {
    constexpr int BIT = 9 - W;
    const ull C = splat2(c), S = splat2(s), NS = splat2(-s);
    if constexpr (BIT >= 5) {
        constexpr int ML = 1 << (BIT - 5);
#pragma unroll
        for (int j = 0; j < 16; j++) {
            ull pr = shx64(vr[j], ML), pi = shx64(vi[j], ML);
            ull nr = fma2(C, vr[j], mul2(S, pi));
            ull ni = fma2(C, vi[j], mul2(NS, pr));
            vr[j] = nr; vi[j] = ni;
        }
    } else if constexpr (BIT >= 1) {
        constexpr int MJ = 1 << (BIT - 1);
#pragma unroll
        for (int j = 0; j < 16; j++) {
            if (!(j & MJ)) {
                const int j1 = j | MJ;
                ull x0r = vr[j], x0i = vi[j], x1r = vr[j1], x1i = vi[j1];
                vr[j]  = fma2(C, x0r, mul2(S, x1i));
                vi[j]  = fma2(C, x0i, mul2(NS, x1r));
                vr[j1] = fma2(C, x1r, mul2(S, x0i));
                vi[j1] = fma2(C, x1i, mul2(NS, x0r));
            }
        }
    } else {
#pragma unroll
        for (int j = 0; j < 16; j++) {
            ull vrs = swap64(vr[j]), vis = swap64(vi[j]);
            vr[j] = fma2(C, vr[j], mul2(S, vis));
            vi[j] = fma2(C, vi[j], mul2(NS, vrs));
        }
    }
}

// ---- CNOT(C, T): new[k] = old[k ^ (bit_C(k) ? mask_T : 0)] ----------------
template <int CQ, int TQ>
__device__ __forceinline__ void cnot_p(ull* vr, ull* vi, int lane) {
    constexpr int BC = 9 - CQ, BT = 9 - TQ;
    if constexpr (BC >= 5 && BT >= 5) {
        // lane ctrl, lane tgt: gather from computed source lane
        constexpr int MCL = 1 << (BC - 5), MTL = 1 << (BT - 5);
        const int src = lane ^ ((lane & MCL) ? MTL : 0);
#pragma unroll
        for (int j = 0; j < 16; j++) {
            vr[j] = shidx64(vr[j], src);
            vi[j] = shidx64(vi[j], src);
        }
    } else if constexpr (BC >= 5 && BT >= 1) {
        // lane ctrl, j tgt: predicated packed-reg swap
        constexpr int MCL = 1 << (BC - 5), MJ = 1 << (BT - 1);
        const bool ctrl = (lane & MCL) != 0;
#pragma unroll
        for (int j = 0; j < 16; j++) {
            if (!(j & MJ)) {
                const int j1 = j | MJ;
                ull a = vr[j], b = vr[j1];
                vr[j] = ctrl ? b : a; vr[j1] = ctrl ? a : b;
                ull p = vi[j], q = vi[j1];
                vi[j] = ctrl ? q : p; vi[j1] = ctrl ? p : q;
            }
        }
    } else if constexpr (BC >= 5) {
        // lane ctrl, half tgt: predicated half swap
        constexpr int MCL = 1 << (BC - 5);
        const bool ctrl = (lane & MCL) != 0;
#pragma unroll
        for (int j = 0; j < 16; j++) {
            ull rs = swap64(vr[j]), is = swap64(vi[j]);
            vr[j] = ctrl ? rs : vr[j];
            vi[j] = ctrl ? is : vi[j];
        }
    } else if constexpr (BC >= 1 && BT >= 5) {
        // j ctrl, lane tgt: exchange across lanes where ctrl bit set
        constexpr int MJ = 1 << (BC - 1), MTL = 1 << (BT - 5);
#pragma unroll
        for (int j = 0; j < 16; j++) {
            if (j & MJ) {
                vr[j] = shx64(vr[j], MTL);
                vi[j] = shx64(vi[j], MTL);
            }
        }
    } else if constexpr (BC >= 1 && BT >= 1) {
        // j ctrl, j tgt: compile-time register permutation
        constexpr int MJ = 1 << (BC - 1), MT = 1 << (BT - 1);
#pragma unroll
        for (int j = 0; j < 16; j++) {
            if ((j & MJ) && !(j & MT)) {
                const int j1 = j | MT;
                ull t;
                t = vr[j]; vr[j] = vr[j1]; vr[j1] = t;
                t = vi[j]; vi[j] = vi[j1]; vi[j1] = t;
            }
        }
    } else if constexpr (BC >= 1) {
        // j ctrl, half tgt: swap halves where ctrl bit set
        constexpr int MJ = 1 << (BC - 1);
#pragma unroll
        for (int j = 0; j < 16; j++) {
            if (j & MJ) { vr[j] = swap64(vr[j]); vi[j] = swap64(vi[j]); }
        }
    } else if constexpr (BT >= 5) {
        // half ctrl, lane tgt: hi halves exchange across lanes
        constexpr int MTL = 1 << (BT - 5);
#pragma unroll
        for (int j = 0; j < 16; j++) {
            float lo, hi;
            unpack2(vr[j], lo, hi);
            hi = shxf(hi, MTL);
            vr[j] = pack2(lo, hi);
            unpack2(vi[j], lo, hi);
            hi = shxf(hi, MTL);
            vi[j] = pack2(lo, hi);
        }
    } else {
        // half ctrl, j tgt: hi halves swap between reg pairs
        constexpr int MT = 1 << (BT - 1);
#pragma unroll
        for (int j = 0; j < 16; j++) {
            if (!(j & MT)) {
                const int j1 = j | MT;
                float l0, h0, l1, h1;
                unpack2(vr[j], l0, h0); unpack2(vr[j1], l1, h1);
                vr[j] = pack2(l0, h1); vr[j1] = pack2(l1, h0);
                unpack2(vi[j], l0, h0); unpack2(vi[j1], l1, h1);
                vi[j] = pack2(l0, h1); vi[j1] = pack2(l1, h0);
            }
        }
    }
}

// ---- compile-time circuit structure ---------------------------------------
template <int L, int W>
__device__ __forceinline__ void layer_rots(ull* vr, ull* vi, int lane,
                                           const float* __restrict__ sg) {
    if constexpr (W < NQ) {
        rot_gate<W>(vr, vi, lane, sg + (L * NQ + W) * 8);
        layer_rots<L, W + 1>(vr, vi, lane, sg);
    }
}
template <int L, int W>
__device__ __forceinline__ void layer_cnots(ull* vr, ull* vi, int lane) {
    if constexpr (W < NQ) {
        cnot_p<W, (W + (L % (NQ - 1)) + 1) % NQ>(vr, vi, lane);
        layer_cnots<L, W + 1>(vr, vi, lane);
    }
}
template <int L>
__device__ __forceinline__ void run_layers(ull* vr, ull* vi, int lane,
                                           const float* __restrict__ sg) {
    if constexpr (L < NL) {
        layer_rots<L, 0>(vr, vi, lane, sg);
        layer_cnots<L, 0>(vr, vi, lane);
        run_layers<L + 1>(vr, vi, lane, sg);
    }
}
template <int W>
__device__ __forceinline__ void init_rx(ull* vr, ull* vi, int lane,
                                        const float* halfang) {
    if constexpr (W < NQ) {
        float s, c;
        __sincosf(halfang[W], &s, &c);
        rx_gate<W>(vr, vi, lane, c, s);
        init_rx<W + 1>(vr, vi, lane, halfang);
    }
}

// ---- main kernel: 8 warps per block, 1 element per warp -------------------
__global__ void __launch_bounds__(256)
qsim_kernel(const float* __restrict__ x, const float* __restrict__ Wm,
            const float* __restrict__ b, const float* __restrict__ weights,
            float* __restrict__ out) {
    __shared__ float sW[NQ * EMB];
    __shared__ float sb[16];
    __shared__ float sg[NL * NQ * 8];

    const int tid = threadIdx.x;
    for (int i = tid; i < NQ * EMB; i += 256) sW[i] = Wm[i];
    if (tid < NQ) sb[tid] = b[tid];
    // build the 60 batch-independent Rot matrices directly in smem
    if (tid < NL * NQ) {
        float phi = weights[tid * 3 + 0];
        float th  = weights[tid * 3 + 1];
        float om  = weights[tid * 3 + 2];
        float c, s;
        sincosf(0.5f * th, &s, &c);
        float a = 0.5f * (phi + om);
        float d = 0.5f * (phi - om);
        float sa, ca, sd, cd;
        sincosf(a, &sa, &ca);
        sincosf(d, &sd, &cd);
        float* g = sg + tid * 8;
        g[0] =  ca * c;  g[1] = -sa * c;
        g[2] = -cd * s;  g[3] = -sd * s;
        g[4] =  cd * s;  g[5] = -sd * s;
        g[6] =  ca * c;  g[7] =  sa * c;
    }
    __syncthreads();

    const int lane = tid & 31;
    const int e = blockIdx.x * 8 + (tid >> 5);

    // angles = x[e] @ W.T + b  (half-angles)
    const float xa = x[e * EMB + lane];
    const float xb = x[e * EMB + 32 + lane];
    float halfang[NQ];
#pragma unroll
    for (int w = 0; w < NQ; w++) {
        float p = xa * sW[w * EMB + lane] + xb * sW[w * EMB + 32 + lane];
#pragma unroll
        for (int m = 16; m >= 1; m >>= 1) p += shxf(p, m);
        halfang[w] = 0.5f * (p + sb[w]);
    }

    // |0...0>
    ull vr[16], vi[16];
#pragma unroll
    for (int j = 0; j < 16; j++) { vr[j] = 0ull; vi[j] = 0ull; }
    if (lane == 0) vr[0] = pack2(1.0f, 0.0f);

    init_rx<0>(vr, vi, lane, halfang);
    run_layers<0>(vr, vi, lane, sg);

    // readout: <Z_q> = sum_k sign_q(k) * |amp_k|^2
    float tot = 0.f, dh = 0.f, d0 = 0.f, d1 = 0.f, d2 = 0.f, d3 = 0.f;
#pragma unroll
    for (int j = 0; j < 16; j++) {
        ull p2 = fma2(vr[j], vr[j], mul2(vi[j], vi[j]));
        float plo, phi;
        unpack2(p2, plo, phi);
        float s = plo + phi;
        float d = plo - phi;
        tot += s;
        dh  += d;
        d0 += (j & 1) ? -s : s;
        d1 += (j & 2) ? -s : s;
        d2 += (j & 4) ? -s : s;
        d3 += (j & 8) ? -s : s;
    }
    float res[NQ];
    // qubits 0..4 on lane bits 4..0
    res[0] = (lane & 16) ? -tot : tot;
    res[1] = (lane & 8)  ? -tot : tot;
    res[2] = (lane & 4)  ? -tot : tot;
    res[3] = (lane & 2)  ? -tot : tot;
    res[4] = (lane & 1)  ? -tot : tot;
    // qubits 5..8 on j bits 3..0; qubit 9 on the packed half
    res[5] = d3; res[6] = d2; res[7] = d1; res[8] = d0; res[9] = dh;
#pragma unroll
    for (int q = 0; q < NQ; q++) {
#pragma unroll
        for (int m = 16; m >= 1; m >>= 1) res[q] += shxf(res[q], m);
    }
#pragma unroll
    for (int q = 0; q < NQ; q++) {
        if (lane == q) out[e * NQ + q] = res[q];
    }
}

extern "C" void kernel_launch(void* const* d_in, const int* in_sizes, int n_in,
                              void* d_out, int out_size) {
    const float* x       = (const float*)d_in[0];  // (16384, 64)
    const float* Wm      = (const float*)d_in[1];  // (10, 64)
    const float* b       = (const float*)d_in[2];  // (10,)
    const float* weights = (const float*)d_in[3];  // (6, 10, 3)
    float* out = (float*)d_out;                    // (16384, 10)

    qsim_kernel<<<BATCH / 8, 256>>>(x, Wm, b, weights, out);
}

// round 4
// speedup vs baseline: 1.7561x; 1.4611x over previous
#include <cuda_runtime.h>
#include <cuda_bf16.h>

// ---------------------------------------------------------------------------
// 10-qubit state-vector simulator, one warp per batch element, f32x2 packed.
// Amplitude index k (10 bits): bits[9:5]=lane, bits[4:1]=j (reg slot),
// bit[0]=half of a packed 64-bit f32x2 value. Qubit w <-> bit (9-w).
// Circuit algebra: Rot = RZ(om) RY(th) RZ(phi); all RZ diagonals are merged
// across CNOT layers into 5 precomputed 1024-entry diagonals G_l; the final
// CNOT layer + final diagonal are folded into the readout sign masks.
// ---------------------------------------------------------------------------

#define NQ 10
#define NL 6
#define BATCH 16384
#define EMB 64

typedef unsigned long long ull;

__device__ float d_G4f[5 * 16 * 32 * 4];  // per (l,j,lane): gr0,gr1,gi0,gi1
__device__ float d_G2f[5 * 16 * 32 * 2];  // per (l,j,lane): -gi0,-gi1
__device__ float d_Yc[100];               // (l-1)*20 + w*2: cos(th/2), sin(th/2), l=1..5
__device__ float d_V0[40];                // w*4: cth0, sth0, cph0, sph0

__device__ __forceinline__ ull pack2(float lo, float hi) {
    ull r; asm("mov.b64 %0, {%1,%2};" : "=l"(r) : "f"(lo), "f"(hi)); return r;
}
__device__ __forceinline__ void unpack2(ull v, float& lo, float& hi) {
    asm("mov.b64 {%0,%1}, %2;" : "=f"(lo), "=f"(hi) : "l"(v));
}
__device__ __forceinline__ ull splat2(float x) { return pack2(x, x); }
__device__ __forceinline__ ull fma2(ull a, ull b, ull c) {
    ull d; asm("fma.rn.f32x2 %0, %1, %2, %3;" : "=l"(d) : "l"(a), "l"(b), "l"(c)); return d;
}
__device__ __forceinline__ ull mul2(ull a, ull b) {
    ull d; asm("mul.rn.f32x2 %0, %1, %2;" : "=l"(d) : "l"(a), "l"(b)); return d;
}
__device__ __forceinline__ ull swap64(ull v) {
    float lo, hi; unpack2(v, lo, hi); return pack2(hi, lo);
}
__device__ __forceinline__ ull shx64(ull v, int m) {
    float lo, hi; unpack2(v, lo, hi);
    lo = __shfl_xor_sync(0xffffffffu, lo, m);
    hi = __shfl_xor_sync(0xffffffffu, hi, m);
    return pack2(lo, hi);
}
__device__ __forceinline__ ull shidx64(ull v, int s) {
    float lo, hi; unpack2(v, lo, hi);
    lo = __shfl_sync(0xffffffffu, lo, s);
    hi = __shfl_sync(0xffffffffu, hi, s);
    return pack2(lo, hi);
}
__device__ __forceinline__ float shxf(float v, int m) {
    return __shfl_xor_sync(0xffffffffu, v, m);
}

// ---- prep kernel: diagonals + coefficients --------------------------------
__global__ void prep_kernel(const float* __restrict__ weights) {
    const int t = threadIdx.x;
    // Y-layer coefficients for layers 1..5
    if (t < 50) {
        int l = t / 10 + 1, w = t % 10;
        float th = weights[l * 30 + w * 3 + 1];
        float s, c; sincosf(0.5f * th, &s, &c);
        d_Yc[(l - 1) * 20 + w * 2]     = c;
        d_Yc[(l - 1) * 20 + w * 2 + 1] = s;
    }
    // layer-0 per-qubit constants for the product-state construction
    if (t >= 64 && t < 74) {
        int w = t - 64;
        float phi = weights[w * 3 + 0];
        float th  = weights[w * 3 + 1];
        float sth, cth, sph, cph;
        sincosf(0.5f * th, &sth, &cth);
        sincosf(0.5f * phi, &sph, &cph);
        d_V0[w * 4] = cth; d_V0[w * 4 + 1] = sth;
        d_V0[w * 4 + 2] = cph; d_V0[w * 4 + 3] = sph;
    }
    // merged diagonals G_l[k] = Dphi(l+1)[k] * Dom(l)[sigma_l^{-1}(k)]
    const int k = t;  // 1024 threads
    for (int l = 0; l < 5; l++) {
        const int r = l + 1;
        int m = k;
        for (int w = 9; w >= 0; w--) {         // reverse CNOT sequence
            int c = w, tt = (w + r) % 10;
            if ((m >> (9 - c)) & 1) m ^= 1 << (9 - tt);
        }
        float e = 0.f;
        for (int w = 0; w < 10; w++) {
            float phi1 = weights[(l + 1) * 30 + w * 3 + 0];
            float om0  = weights[l * 30 + w * 3 + 2];
            e += 0.5f * phi1 * (((k >> (9 - w)) & 1) ? 1.f : -1.f);
            e += 0.5f * om0  * (((m >> (9 - w)) & 1) ? 1.f : -1.f);
        }
        float gi, gr; sincosf(e, &gi, &gr);
        const int lane = k >> 5, j = (k >> 1) & 15, half = k & 1;
        const int b4 = ((l * 16 + j) * 32 + lane) * 4;
        d_G4f[b4 + half]     = gr;
        d_G4f[b4 + 2 + half] = gi;
        const int b2 = ((l * 16 + j) * 32 + lane) * 2;
        d_G2f[b2 + half] = -gi;
    }
}

// ---- real RY gate on qubit W ----------------------------------------------
template <int W>
__device__ __forceinline__ void y_gate(ull* vr, ull* vi, int lane, float c, float s) {
    constexpr int BIT = 9 - W;
    const ull C = splat2(c);
    if constexpr (BIT >= 5) {
        constexpr int ML = 1 << (BIT - 5);
        const ull SG = splat2((lane & ML) ? s : -s);
#pragma unroll
        for (int j = 0; j < 16; j++) {
            ull pr = shx64(vr[j], ML), pi = shx64(vi[j], ML);
            vr[j] = fma2(C, vr[j], mul2(SG, pr));
            vi[j] = fma2(C, vi[j], mul2(SG, pi));
        }
    } else if constexpr (BIT >= 1) {
        constexpr int MJ = 1 << (BIT - 1);
        const ull S = splat2(s), NS = splat2(-s);
#pragma unroll
        for (int j = 0; j < 16; j++) {
            if (!(j & MJ)) {
                const int j1 = j | MJ;
                ull x0r = vr[j], x0i = vi[j], x1r = vr[j1], x1i = vi[j1];
                vr[j]  = fma2(C, x0r, mul2(NS, x1r));
                vi[j]  = fma2(C, x0i, mul2(NS, x1i));
                vr[j1] = fma2(C, x1r, mul2(S, x0r));
                vi[j1] = fma2(C, x1i, mul2(S, x0i));
            }
        }
    } else {
        const ull SP = pack2(-s, s);
#pragma unroll
        for (int j = 0; j < 16; j++) {
            vr[j] = fma2(C, vr[j], mul2(SP, swap64(vr[j])));
            vi[j] = fma2(C, vi[j], mul2(SP, swap64(vi[j])));
        }
    }
}

// ---- CNOT(C, T): new[k] = old[k ^ (bit_C(k) ? mask_T : 0)] ----------------
template <int CQ, int TQ>
__device__ __forceinline__ void cnot_p(ull* vr, ull* vi, int lane) {
    constexpr int BC = 9 - CQ, BT = 9 - TQ;
    if constexpr (BC >= 5 && BT >= 5) {
        constexpr int MCL = 1 << (BC - 5), MTL = 1 << (BT - 5);
        const int src = lane ^ ((lane & MCL) ? MTL : 0);
#pragma unroll
        for (int j = 0; j < 16; j++) {
            vr[j] = shidx64(vr[j], src);
            vi[j] = shidx64(vi[j], src);
        }
    } else if constexpr (BC >= 5 && BT >= 1) {
        constexpr int MCL = 1 << (BC - 5), MJ = 1 << (BT - 1);
        const bool ctrl = (lane & MCL) != 0;
#pragma unroll
        for (int j = 0; j < 16; j++) {
            if (!(j & MJ)) {
                const int j1 = j | MJ;
                ull a = vr[j], b = vr[j1];
                vr[j] = ctrl ? b : a; vr[j1] = ctrl ? a : b;
                ull p = vi[j], q = vi[j1];
                vi[j] = ctrl ? q : p; vi[j1] = ctrl ? p : q;
            }
        }
    } else if constexpr (BC >= 5) {
        constexpr int MCL = 1 << (BC - 5);
        const bool ctrl = (lane & MCL) != 0;
#pragma unroll
        for (int j = 0; j < 16; j++) {
            ull rs = swap64(vr[j]), is = swap64(vi[j]);
            vr[j] = ctrl ? rs : vr[j];
            vi[j] = ctrl ? is : vi[j];
        }
    } else if constexpr (BC >= 1 && BT >= 5) {
        constexpr int MJ = 1 << (BC - 1), MTL = 1 << (BT - 5);
#pragma unroll
        for (int j = 0; j < 16; j++) {
            if (j & MJ) {
                vr[j] = shx64(vr[j], MTL);
                vi[j] = shx64(vi[j], MTL);
            }
        }
    } else if constexpr (BC >= 1 && BT >= 1) {
        constexpr int MJ = 1 << (BC - 1), MT = 1 << (BT - 1);
#pragma unroll
        for (int j = 0; j < 16; j++) {
            if ((j & MJ) && !(j & MT)) {
                const int j1 = j | MT;
                ull t;
                t = vr[j]; vr[j] = vr[j1]; vr[j1] = t;
                t = vi[j]; vi[j] = vi[j1]; vi[j1] = t;
            }
        }
    } else if constexpr (BC >= 1) {
        constexpr int MJ = 1 << (BC - 1);
#pragma unroll
        for (int j = 0; j < 16; j++) {
            if (j & MJ) { vr[j] = swap64(vr[j]); vi[j] = swap64(vi[j]); }
        }
    } else if constexpr (BT >= 5) {
        constexpr int MTL = 1 << (BT - 5);
#pragma unroll
        for (int j = 0; j < 16; j++) {
            float lo, hi;
            unpack2(vr[j], lo, hi);
            hi = shxf(hi, MTL);
            vr[j] = pack2(lo, hi);
            unpack2(vi[j], lo, hi);
            hi = shxf(hi, MTL);
            vi[j] = pack2(lo, hi);
        }
    } else {
        constexpr int MT = 1 << (BT - 1);
#pragma unroll
        for (int j = 0; j < 16; j++) {
            if (!(j & MT)) {
                const int j1 = j | MT;
                float l0, h0, l1, h1;
                unpack2(vr[j], l0, h0); unpack2(vr[j1], l1, h1);
                vr[j] = pack2(l0, h1); vr[j1] = pack2(l1, h0);
                unpack2(vi[j], l0, h0); unpack2(vi[j1], l1, h1);
                vi[j] = pack2(l0, h1); vi[j1] = pack2(l1, h0);
            }
        }
    }
}

// ---- merged diagonal pass --------------------------------------------------
__device__ __forceinline__ void apply_G(ull* vr, ull* vi,
                                        const float4* __restrict__ sG4,
                                        const float2* __restrict__ sG2,
                                        int base) {
#pragma unroll
    for (int j = 0; j < 16; j++) {
        float4 g = sG4[base + j * 32];
        float2 n = sG2[base + j * 32];
        ull GR = pack2(g.x, g.y), GI = pack2(g.z, g.w), NGI = pack2(n.x, n.y);
        ull nr = fma2(GR, vr[j], mul2(NGI, vi[j]));
        ull ni = fma2(GR, vi[j], mul2(GI, vr[j]));
        vr[j] = nr; vi[j] = ni;
    }
}

// ---- compile-time layer structure -----------------------------------------
template <int L, int W>
__device__ __forceinline__ void layer_cnots(ull* vr, ull* vi, int lane) {
    if constexpr (W < NQ) {
        cnot_p<W, (W + (L % (NQ - 1)) + 1) % NQ>(vr, vi, lane);
        layer_cnots<L, W + 1>(vr, vi, lane);
    }
}
template <int L, int W>
__device__ __forceinline__ void y_layer(ull* vr, ull* vi, int lane,
                                        const float* __restrict__ sY) {
    if constexpr (W < NQ) {
        y_gate<W>(vr, vi, lane, sY[(L - 1) * 20 + W * 2], sY[(L - 1) * 20 + W * 2 + 1]);
        y_layer<L, W + 1>(vr, vi, lane, sY);
    }
}
template <int L>
__device__ __forceinline__ void run_layers(ull* vr, ull* vi, int lane,
                                           const float4* __restrict__ sG4,
                                           const float2* __restrict__ sG2,
                                           const float* __restrict__ sY) {
    if constexpr (L < 5) {
        layer_cnots<L, 0>(vr, vi, lane);
        apply_G(vr, vi, sG4, sG2, L * 512 + lane);
        y_layer<L + 1, 0>(vr, vi, lane, sY);
        run_layers<L + 1>(vr, vi, lane, sG4, sG2, sY);
    }
}

__device__ __forceinline__ float wht5(float v, int lane) {
#pragma unroll
    for (int m = 1; m < 32; m <<= 1) {
        float u = shxf(v, m);
        v = (lane & m) ? (u - v) : (u + v);
    }
    return v;
}

// ---- main kernel: 8 warps per block, 1 element per warp -------------------
__global__ void __launch_bounds__(256)
qsim_kernel(const float* __restrict__ x, const float* __restrict__ Wm,
            const float* __restrict__ b, float* __restrict__ out) {
    extern __shared__ float smem[];
    float* sG4f = smem;                 // 10240 floats
    float* sG2f = smem + 10240;         // 5120
    float* sW   = smem + 15360;         // 640
    float* sY   = smem + 16000;         // 100
    float* sV   = smem + 16100;         // 40
    float* sb   = smem + 16140;         // 16

    const int tid = threadIdx.x;
    {
        float4* d4 = (float4*)sG4f;
        const float4* s4 = (const float4*)d_G4f;
        for (int i = tid; i < 2560; i += 256) d4[i] = s4[i];
        float2* d2 = (float2*)sG2f;
        const float2* s2 = (const float2*)d_G2f;
        for (int i = tid; i < 2560; i += 256) d2[i] = s2[i];
        for (int i = tid; i < NQ * EMB; i += 256) sW[i] = Wm[i];
        if (tid < 100) sY[tid] = d_Yc[tid];
        if (tid < 40) sV[tid] = d_V0[tid];
        if (tid < 16) sb[tid] = (tid < NQ) ? b[tid] : 0.f;
    }
    __syncthreads();

    const int lane = tid & 31;
    const int e = blockIdx.x * 8 + (tid >> 5);

    // angles = x[e] @ W.T + b  (half-angles)
    const float xa = x[e * EMB + lane];
    const float xb = x[e * EMB + 32 + lane];
    float halfang[NQ];
#pragma unroll
    for (int w = 0; w < NQ; w++) {
        float p = xa * sW[w * EMB + lane] + xb * sW[w * EMB + 32 + lane];
#pragma unroll
        for (int m = 16; m >= 1; m >>= 1) p += shxf(p, m);
        halfang[w] = 0.5f * (p + sb[w]);
    }

    // per-qubit vectors v_w = RY(th0) RZ(phi0) RX(a) |0>
    float v0r[NQ], v0i[NQ], v1r[NQ], v1i[NQ];
#pragma unroll
    for (int w = 0; w < NQ; w++) {
        float sa, ca; __sincosf(halfang[w], &sa, &ca);
        float cth = sV[w * 4], sth = sV[w * 4 + 1];
        float cph = sV[w * 4 + 2], sph = sV[w * 4 + 3];
        float P = ca * cph, Q = ca * sph, R = sa * cph, T = sa * sph;
        v0r[w] = cth * P - sth * T;
        v0i[w] = sth * R - cth * Q;
        v1r[w] = sth * P + cth * T;
        v1i[w] = -sth * Q - cth * R;
    }

    // lane factor: qubits 0..4 on lane bits 4..0
    float plr = (lane & 16) ? v1r[0] : v0r[0];
    float pli = (lane & 16) ? v1i[0] : v0i[0];
#pragma unroll
    for (int w = 1; w < 5; w++) {
        const int m = 1 << (4 - w);
        float tr = (lane & m) ? v1r[w] : v0r[w];
        float ti = (lane & m) ? v1i[w] : v0i[w];
        float nr = plr * tr - pli * ti;
        float ni = plr * ti + pli * tr;
        plr = nr; pli = ni;
    }

    // register factors: qubits 5..8 on j bits 3..0 (doubling build)
    float rr[16], ri[16];
    rr[0] = v0r[5]; ri[0] = v0i[5];
    rr[8] = v1r[5]; ri[8] = v1i[5];
#pragma unroll
    for (int base = 0; base <= 8; base += 8) {
        float ar = rr[base], ai = ri[base];
        rr[base + 4] = ar * v1r[6] - ai * v1i[6];
        ri[base + 4] = ar * v1i[6] + ai * v1r[6];
        rr[base]     = ar * v0r[6] - ai * v0i[6];
        ri[base]     = ar * v0i[6] + ai * v0r[6];
    }
#pragma unroll
    for (int base = 0; base <= 12; base += 4) {
        float ar = rr[base], ai = ri[base];
        rr[base + 2] = ar * v1r[7] - ai * v1i[7];
        ri[base + 2] = ar * v1i[7] + ai * v1r[7];
        rr[base]     = ar * v0r[7] - ai * v0i[7];
        ri[base]     = ar * v0i[7] + ai * v0r[7];
    }
#pragma unroll
    for (int base = 0; base <= 14; base += 2) {
        float ar = rr[base], ai = ri[base];
        rr[base + 1] = ar * v1r[8] - ai * v1i[8];
        ri[base + 1] = ar * v1i[8] + ai * v1r[8];
        rr[base]     = ar * v0r[8] - ai * v0i[8];
        ri[base]     = ar * v0i[8] + ai * v0r[8];
    }
    // fold the lane factor, then tensor with qubit 9 (packed half)
    ull vr[16], vi[16];
    const ull V9R  = pack2(v0r[9], v1r[9]);
    const ull V9I  = pack2(v0i[9], v1i[9]);
    const ull NV9I = pack2(-v0i[9], -v1i[9]);
#pragma unroll
    for (int j = 0; j < 16; j++) {
        float ar = plr * rr[j] - pli * ri[j];
        float ai = plr * ri[j] + pli * rr[j];
        ull AR = splat2(ar), AI = splat2(ai);
        vr[j] = fma2(AR, V9R, mul2(AI, NV9I));
        vi[j] = fma2(AR, V9I, mul2(AI, V9R));
    }

    // 5 x [CNOT layer, merged diagonal, RY layer]; C5 + final phase folded out
    run_layers<0>(vr, vi, lane, (const float4*)sG4f, (const float2*)sG2f, sY);

    // readout with sigma_5-adjusted Walsh masks
    float a0 = 0.f, a1 = 0.f, a2 = 0.f, a3 = 0.f, a4 = 0.f, a5 = 0.f, a6 = 0.f;
#pragma unroll
    for (int j = 0; j < 16; j++) {
        ull p2 = fma2(vr[j], vr[j], mul2(vi[j], vi[j]));
        float plo, phi_; unpack2(p2, plo, phi_);
        float s = plo + phi_;
        float d = plo - phi_;
        a0 += s;
        a1 += (j & 8) ? -s : s;
        a2 += (j & 4) ? -s : s;
        a3 += (j & 2) ? -s : s;
        a4 += (j & 1) ? -s : s;
        a5 += (j & 8) ? -d : d;
        a6 += d;
    }
    a0 = wht5(a0, lane);
    a1 = wht5(a1, lane);
    a2 = wht5(a2, lane);
    a3 = wht5(a3, lane);
    a4 = wht5(a4, lane);
    a5 = wht5(a5, lane);
    a6 = wht5(a6, lane);

    float* o = out + e * NQ;
    if (lane == 17) o[0] = a0;                 // q0: L={4,0}
    if (lane == 8)  { o[1] = a1; o[7] = a3; }  // q1: L={3},J=8 ; q7: L={3},J=2
    if (lane == 20) o[2] = a2;                 // q2: L={4,2},J=4
    if (lane == 10) o[3] = a3;                 // q3: L={3,1},J=2
    if (lane == 5)  o[4] = a4;                 // q4: L={2,0},J=1
    if (lane == 2)  { o[5] = a5; o[9] = a6; }  // q5: L={1},J=8,H ; q9: L={1},H
    if (lane == 16) o[6] = a2;                 // q6: L={4},J=4
    if (lane == 4)  o[8] = a4;                 // q8: L={2},J=1
}

extern "C" void kernel_launch(void* const* d_in, const int* in_sizes, int n_in,
                              void* d_out, int out_size) {
    const float* x       = (const float*)d_in[0];  // (16384, 64)
    const float* Wm      = (const float*)d_in[1];  // (10, 64)
    const float* b       = (const float*)d_in[2];  // (10,)
    const float* weights = (const float*)d_in[3];  // (6, 10, 3)
    float* out = (float*)d_out;                    // (16384, 10)

    const int smem_bytes = (16140 + 16) * sizeof(float);
    cudaFuncSetAttribute(qsim_kernel,
                         cudaFuncAttributeMaxDynamicSharedMemorySize, smem_bytes);

    prep_kernel<<<1, 1024>>>(weights);
    qsim_kernel<<<BATCH / 8, 256, smem_bytes>>>(x, Wm, b, out);
}

// round 5
// speedup vs baseline: 2.1377x; 1.2173x over previous
#include <cuda_runtime.h>
#include <cuda_bf16.h>

// ---------------------------------------------------------------------------
// 10-qubit state-vector simulator, one warp per batch element, f32x2 packed.
// Amplitude index k (10 bits): bits[9:5]=lane, bits[4:1]=j (reg slot),
// bit[0]=half of a packed 64-bit f32x2 value. Qubit w <-> bit (9-w).
// Circuit: [product state] then 5 x [CNOT layer, merged diagonal G_l, RY layer];
// the final CNOT layer + final diagonal are folded into the readout masks.
// CNOT layers use merged gathers: leading lane/lane CNOTs compose into one
// lane permutation; trailing reg-ctrl/lane-tgt CNOTs fuse into per-(j,half)
// compile-time XOR lane masks.
// ---------------------------------------------------------------------------

#define NQ 10
#define NL 6
#define BATCH 16384
#define EMB 64

typedef unsigned long long ull;

__device__ float d_G4f[5 * 16 * 32 * 4];  // per (l,j,lane): gr0,gr1,gi0,gi1
__device__ float d_Yc[100];               // (l-1)*20 + w*2: cos(th/2), sin(th/2), l=1..5
__device__ float d_V0[40];                // w*4: cth0, sth0, cph0, sph0

__device__ __forceinline__ ull pack2(float lo, float hi) {
    ull r; asm("mov.b64 %0, {%1,%2};" : "=l"(r) : "f"(lo), "f"(hi)); return r;
}
__device__ __forceinline__ void unpack2(ull v, float& lo, float& hi) {
    asm("mov.b64 {%0,%1}, %2;" : "=f"(lo), "=f"(hi) : "l"(v));
}
__device__ __forceinline__ ull splat2(float x) { return pack2(x, x); }
__device__ __forceinline__ ull fma2(ull a, ull b, ull c) {
    ull d; asm("fma.rn.f32x2 %0, %1, %2, %3;" : "=l"(d) : "l"(a), "l"(b), "l"(c)); return d;
}
__device__ __forceinline__ ull mul2(ull a, ull b) {
    ull d; asm("mul.rn.f32x2 %0, %1, %2;" : "=l"(d) : "l"(a), "l"(b)); return d;
}
__device__ __forceinline__ ull swap64(ull v) {
    float lo, hi; unpack2(v, lo, hi); return pack2(hi, lo);
}
__device__ __forceinline__ ull shx64(ull v, int m) {
    float lo, hi; unpack2(v, lo, hi);
    lo = __shfl_xor_sync(0xffffffffu, lo, m);
    hi = __shfl_xor_sync(0xffffffffu, hi, m);
    return pack2(lo, hi);
}
__device__ __forceinline__ ull shidx64(ull v, int s) {
    float lo, hi; unpack2(v, lo, hi);
    lo = __shfl_sync(0xffffffffu, lo, s);
    hi = __shfl_sync(0xffffffffu, hi, s);
    return pack2(lo, hi);
}
__device__ __forceinline__ float shxf(float v, int m) {
    return __shfl_xor_sync(0xffffffffu, v, m);
}

// ---- prep kernel: diagonals + coefficients --------------------------------
__global__ void prep_kernel(const float* __restrict__ weights) {
    const int t = threadIdx.x;
    if (t < 50) {
        int l = t / 10 + 1, w = t % 10;
        float th = weights[l * 30 + w * 3 + 1];
        float s, c; sincosf(0.5f * th, &s, &c);
        d_Yc[(l - 1) * 20 + w * 2]     = c;
        d_Yc[(l - 1) * 20 + w * 2 + 1] = s;
    }
    if (t >= 64 && t < 74) {
        int w = t - 64;
        float phi = weights[w * 3 + 0];
        float th  = weights[w * 3 + 1];
        float sth, cth, sph, cph;
        sincosf(0.5f * th, &sth, &cth);
        sincosf(0.5f * phi, &sph, &cph);
        d_V0[w * 4] = cth; d_V0[w * 4 + 1] = sth;
        d_V0[w * 4 + 2] = cph; d_V0[w * 4 + 3] = sph;
    }
    // merged diagonals G_l[k] = Dphi(l+1)[k] * Dom(l)[sigma_l^{-1}(k)]
    const int k = t;  // 1024 threads
    for (int l = 0; l < 5; l++) {
        const int r = l + 1;
        int m = k;
        for (int w = 9; w >= 0; w--) {
            int c = w, tt = (w + r) % 10;
            if ((m >> (9 - c)) & 1) m ^= 1 << (9 - tt);
        }
        float e = 0.f;
        for (int w = 0; w < 10; w++) {
            float phi1 = weights[(l + 1) * 30 + w * 3 + 0];
            float om0  = weights[l * 30 + w * 3 + 2];
            e += 0.5f * phi1 * (((k >> (9 - w)) & 1) ? 1.f : -1.f);
            e += 0.5f * om0  * (((m >> (9 - w)) & 1) ? 1.f : -1.f);
        }
        float gi, gr; sincosf(e, &gi, &gr);
        const int lane = k >> 5, j = (k >> 1) & 15, half = k & 1;
        const int b4 = ((l * 16 + j) * 32 + lane) * 4;
        d_G4f[b4 + half]     = gr;
        d_G4f[b4 + 2 + half] = gi;
    }
}

// ---- real RY gate on qubit W ----------------------------------------------
template <int W>
__device__ __forceinline__ void y_gate(ull* vr, ull* vi, int lane, float c, float s) {
    constexpr int BIT = 9 - W;
    const ull C = splat2(c);
    if constexpr (BIT >= 5) {
        constexpr int ML = 1 << (BIT - 5);
        const ull SG = splat2((lane & ML) ? s : -s);
#pragma unroll
        for (int j = 0; j < 16; j++) {
            ull pr = shx64(vr[j], ML), pi = shx64(vi[j], ML);
            vr[j] = fma2(C, vr[j], mul2(SG, pr));
            vi[j] = fma2(C, vi[j], mul2(SG, pi));
        }
    } else if constexpr (BIT >= 1) {
        constexpr int MJ = 1 << (BIT - 1);
        const ull S = splat2(s), NS = splat2(-s);
#pragma unroll
        for (int j = 0; j < 16; j++) {
            if (!(j & MJ)) {
                const int j1 = j | MJ;
                ull x0r = vr[j], x0i = vi[j], x1r = vr[j1], x1i = vi[j1];
                vr[j]  = fma2(C, x0r, mul2(NS, x1r));
                vi[j]  = fma2(C, x0i, mul2(NS, x1i));
                vr[j1] = fma2(C, x1r, mul2(S, x0r));
                vi[j1] = fma2(C, x1i, mul2(S, x0i));
            }
        }
    } else {
        const ull SP = pack2(-s, s);
#pragma unroll
        for (int j = 0; j < 16; j++) {
            vr[j] = fma2(C, vr[j], mul2(SP, swap64(vr[j])));
            vi[j] = fma2(C, vi[j], mul2(SP, swap64(vi[j])));
        }
    }
}

// ---- individual CNOT(C, T) for the middle (reg-target) group --------------
template <int CQ, int TQ>
__device__ __forceinline__ void cnot_p(ull* vr, ull* vi, int lane) {
    constexpr int BC = 9 - CQ, BT = 9 - TQ;
    if constexpr (BC >= 5 && BT >= 1) {
        // lane ctrl, j tgt: predicated packed-reg swap
        constexpr int MCL = 1 << (BC - 5), MJ = 1 << (BT - 1);
        const bool ctrl = (lane & MCL) != 0;
#pragma unroll
        for (int j = 0; j < 16; j++) {
            if (!(j & MJ)) {
                const int j1 = j | MJ;
                ull a = vr[j], b = vr[j1];
                vr[j] = ctrl ? b : a; vr[j1] = ctrl ? a : b;
                ull p = vi[j], q = vi[j1];
                vi[j] = ctrl ? q : p; vi[j1] = ctrl ? p : q;
            }
        }
    } else if constexpr (BC >= 5) {
        // lane ctrl, half tgt: predicated half swap
        constexpr int MCL = 1 << (BC - 5);
        const bool ctrl = (lane & MCL) != 0;
#pragma unroll
        for (int j = 0; j < 16; j++) {
            ull rs = swap64(vr[j]), is = swap64(vi[j]);
            vr[j] = ctrl ? rs : vr[j];
            vi[j] = ctrl ? is : vi[j];
        }
    } else if constexpr (BC >= 1 && BT >= 1) {
        // j ctrl, j tgt: compile-time register permutation
        constexpr int MJ = 1 << (BC - 1), MT = 1 << (BT - 1);
#pragma unroll
        for (int j = 0; j < 16; j++) {
            if ((j & MJ) && !(j & MT)) {
                const int j1 = j | MT;
                ull t;
                t = vr[j]; vr[j] = vr[j1]; vr[j1] = t;
                t = vi[j]; vi[j] = vi[j1]; vi[j1] = t;
            }
        }
    } else if constexpr (BC >= 1) {
        // j ctrl, half tgt: swap halves where ctrl bit set
        constexpr int MJ = 1 << (BC - 1);
#pragma unroll
        for (int j = 0; j < 16; j++) {
            if (j & MJ) { vr[j] = swap64(vr[j]); vi[j] = swap64(vi[j]); }
        }
    }
}

// ---- merged leading lane/lane group (CNOT(w,w+R) for w=0..M-1) -----------
// new[k] = old[F0(F1(...F_{M-1}(k)))]; apply involutions innermost-first.
template <int R, int M>
__device__ __forceinline__ void cnot_ll_group(ull* vr, ull* vi, int lane) {
    int s = lane;
#pragma unroll
    for (int w = M - 1; w >= 0; w--) {
        s ^= ((s >> (4 - w)) & 1) << (4 - w - R);
    }
#pragma unroll
    for (int j = 0; j < 16; j++) {
        vr[j] = shidx64(vr[j], s);
        vi[j] = shidx64(vi[j], s);
    }
}

// ---- merged trailing reg-ctrl/lane-tgt group ------------------------------
// For w in [10-R, 9]: CNOT(w, (w+R)%10); controls are index bits of (j,half),
// targets are lane bits; all commute -> single XOR lane mask per (j,half).
__device__ constexpr int trail_mask_ct(int R, int j, int h) {
    int m = 0;
    for (int w = 5; w <= 9; w++) {
        int t = (w + R) % 10;
        if (w + R >= 10 && t <= 4) {
            int bit = (w == 9) ? h : ((j >> (8 - w)) & 1);
            if (bit) m ^= 16 >> t;
        }
    }
    return m;
}
template <int R, int J>
__device__ __forceinline__ void cnot_trail_j(ull* vr, ull* vi) {
    if constexpr (J < 16) {
        constexpr int mlo = trail_mask_ct(R, J, 0);
        constexpr int mhi = trail_mask_ct(R, J, 1);
        if constexpr (mlo != 0 || mhi != 0) {
            float rlo, rhi, ilo, ihi;
            unpack2(vr[J], rlo, rhi);
            unpack2(vi[J], ilo, ihi);
            if constexpr (mlo != 0) { rlo = shxf(rlo, mlo); ilo = shxf(ilo, mlo); }
            if constexpr (mhi != 0) { rhi = shxf(rhi, mhi); ihi = shxf(ihi, mhi); }
            vr[J] = pack2(rlo, rhi);
            vi[J] = pack2(ilo, ihi);
        }
        cnot_trail_j<R, J + 1>(vr, vi);
    }
}

// ---- middle sequential CNOTs (reg targets) --------------------------------
template <int L, int W, int WEND>
__device__ __forceinline__ void cnots_seq(ull* vr, ull* vi, int lane) {
    if constexpr (W <= WEND) {
        cnot_p<W, (W + L % 9 + 1) % 10>(vr, vi, lane);
        cnots_seq<L, W + 1, WEND>(vr, vi, lane);
    }
}

template <int L>
__device__ __forceinline__ void cnot_layer(ull* vr, ull* vi, int lane) {
    constexpr int R = L + 1;
    if constexpr (R <= 4) cnot_ll_group<R, 5 - R>(vr, vi, lane);
    cnots_seq<L, 5 - R, 9 - R>(vr, vi, lane);
    cnot_trail_j<R, 0>(vr, vi);
}

// ---- merged diagonal pass (-gi via packed sign flip) -----------------------
__device__ __forceinline__ void apply_G(ull* vr, ull* vi,
                                        const ulonglong2* __restrict__ sG,
                                        int base) {
#pragma unroll
    for (int j = 0; j < 16; j++) {
        ulonglong2 g = sG[base + j * 32];
        ull GR = g.x, GI = g.y;
        ull NGI = GI ^ 0x8000000080000000ULL;
        ull nr = fma2(GR, vr[j], mul2(NGI, vi[j]));
        ull ni = fma2(GR, vi[j], mul2(GI, vr[j]));
        vr[j] = nr; vi[j] = ni;
    }
}

// ---- compile-time layer structure -----------------------------------------
template <int L, int W>
__device__ __forceinline__ void y_layer(ull* vr, ull* vi, int lane,
                                        const float* __restrict__ sY) {
    if constexpr (W < NQ) {
        y_gate<W>(vr, vi, lane, sY[(L - 1) * 20 + W * 2], sY[(L - 1) * 20 + W * 2 + 1]);
        y_layer<L, W + 1>(vr, vi, lane, sY);
    }
}
template <int L>
__device__ __forceinline__ void run_layers(ull* vr, ull* vi, int lane,
                                           const ulonglong2* __restrict__ sG,
                                           const float* __restrict__ sY) {
    if constexpr (L < 5) {
        cnot_layer<L>(vr, vi, lane);
        apply_G(vr, vi, sG, L * 512 + lane);
        y_layer<L + 1, 0>(vr, vi, lane, sY);
        run_layers<L + 1>(vr, vi, lane, sG, sY);
    }
}

__device__ __forceinline__ float wht5(float v, int lane) {
#pragma unroll
    for (int m = 1; m < 32; m <<= 1) {
        float u = shxf(v, m);
        v = (lane & m) ? (u - v) : (u + v);
    }
    return v;
}

// ---- main kernel: 8 warps per block, 1 element per warp -------------------
__global__ void __launch_bounds__(256)
qsim_kernel(const float* __restrict__ x, const float* __restrict__ Wm,
            const float* __restrict__ b, float* __restrict__ out) {
    extern __shared__ float smem[];
    float* sG4f = smem;                 // 10240 floats (ull2 view)
    float* sW   = smem + 10240;         // 640
    float* sY   = smem + 10880;         // 100
    float* sV   = smem + 10980;         // 40
    float* sb   = smem + 11020;         // 16

    const int tid = threadIdx.x;
    {
        float4* d4 = (float4*)sG4f;
        const float4* s4 = (const float4*)d_G4f;
        for (int i = tid; i < 2560; i += 256) d4[i] = s4[i];
        for (int i = tid; i < NQ * EMB; i += 256) sW[i] = Wm[i];
        if (tid < 100) sY[tid] = d_Yc[tid];
        if (tid < 40) sV[tid] = d_V0[tid];
        if (tid < 16) sb[tid] = (tid < NQ) ? b[tid] : 0.f;
    }
    __syncthreads();

    const int lane = tid & 31;
    const int e = blockIdx.x * 8 + (tid >> 5);

    // angles = x[e] @ W.T + b  (half-angles)
    const float xa = x[e * EMB + lane];
    const float xb = x[e * EMB + 32 + lane];
    float halfang[NQ];
#pragma unroll
    for (int w = 0; w < NQ; w++) {
        float p = xa * sW[w * EMB + lane] + xb * sW[w * EMB + 32 + lane];
#pragma unroll
        for (int m = 16; m >= 1; m >>= 1) p += shxf(p, m);
        halfang[w] = 0.5f * (p + sb[w]);
    }

    // per-qubit vectors v_w = RY(th0) RZ(phi0) RX(a) |0>
    float v0r[NQ], v0i[NQ], v1r[NQ], v1i[NQ];
#pragma unroll
    for (int w = 0; w < NQ; w++) {
        float sa, ca; __sincosf(halfang[w], &sa, &ca);
        float cth = sV[w * 4], sth = sV[w * 4 + 1];
        float cph = sV[w * 4 + 2], sph = sV[w * 4 + 3];
        float P = ca * cph, Q = ca * sph, R = sa * cph, T = sa * sph;
        v0r[w] = cth * P - sth * T;
        v0i[w] = sth * R - cth * Q;
        v1r[w] = sth * P + cth * T;
        v1i[w] = -sth * Q - cth * R;
    }

    // lane factor: qubits 0..4 on lane bits 4..0
    float plr = (lane & 16) ? v1r[0] : v0r[0];
    float pli = (lane & 16) ? v1i[0] : v0i[0];
#pragma unroll
    for (int w = 1; w < 5; w++) {
        const int m = 1 << (4 - w);
        float tr = (lane & m) ? v1r[w] : v0r[w];
        float ti = (lane & m) ? v1i[w] : v0i[w];
        float nr = plr * tr - pli * ti;
        float ni = plr * ti + pli * tr;
        plr = nr; pli = ni;
    }

    // register factors: qubits 5..8 on j bits 3..0 (doubling build)
    float rr[16], ri[16];
    rr[0] = v0r[5]; ri[0] = v0i[5];
    rr[8] = v1r[5]; ri[8] = v1i[5];
#pragma unroll
    for (int base = 0; base <= 8; base += 8) {
        float ar = rr[base], ai = ri[base];
        rr[base + 4] = ar * v1r[6] - ai * v1i[6];
        ri[base + 4] = ar * v1i[6] + ai * v1r[6];
        rr[base]     = ar * v0r[6] - ai * v0i[6];
        ri[base]     = ar * v0i[6] + ai * v0r[6];
    }
#pragma unroll
    for (int base = 0; base <= 12; base += 4) {
        float ar = rr[base], ai = ri[base];
        rr[base + 2] = ar * v1r[7] - ai * v1i[7];
        ri[base + 2] = ar * v1i[7] + ai * v1r[7];
        rr[base]     = ar * v0r[7] - ai * v0i[7];
        ri[base]     = ar * v0i[7] + ai * v0r[7];
    }
#pragma unroll
    for (int base = 0; base <= 14; base += 2) {
        float ar = rr[base], ai = ri[base];
        rr[base + 1] = ar * v1r[8] - ai * v1i[8];
        ri[base + 1] = ar * v1i[8] + ai * v1r[8];
        rr[base]     = ar * v0r[8] - ai * v0i[8];
        ri[base]     = ar * v0i[8] + ai * v0r[8];
    }
    // fold the lane factor, then tensor with qubit 9 (packed half)
    ull vr[16], vi[16];
    const ull V9R  = pack2(v0r[9], v1r[9]);
    const ull V9I  = pack2(v0i[9], v1i[9]);
    const ull NV9I = pack2(-v0i[9], -v1i[9]);
#pragma unroll
    for (int j = 0; j < 16; j++) {
        float ar = plr * rr[j] - pli * ri[j];
        float ai = plr * ri[j] + pli * rr[j];
        ull AR = splat2(ar), AI = splat2(ai);
        vr[j] = fma2(AR, V9R, mul2(AI, NV9I));
        vi[j] = fma2(AR, V9I, mul2(AI, V9R));
    }

    // 5 x [CNOT layer, merged diagonal, RY layer]; C5 + final phase folded out
    run_layers<0>(vr, vi, lane, (const ulonglong2*)sG4f, sY);

    // readout with sigma_5-adjusted Walsh masks
    float a0 = 0.f, a1 = 0.f, a2 = 0.f, a3 = 0.f, a4 = 0.f, a5 = 0.f, a6 = 0.f;
#pragma unroll
    for (int j = 0; j < 16; j++) {
        ull p2 = fma2(vr[j], vr[j], mul2(vi[j], vi[j]));
        float plo, phi_; unpack2(p2, plo, phi_);
        float s = plo + phi_;
        float d = plo - phi_;
        a0 += s;
        a1 += (j & 8) ? -s : s;
        a2 += (j & 4) ? -s : s;
        a3 += (j & 2) ? -s : s;
        a4 += (j & 1) ? -s : s;
        a5 += (j & 8) ? -d : d;
        a6 += d;
    }
    a0 = wht5(a0, lane);
    a1 = wht5(a1, lane);
    a2 = wht5(a2, lane);
    a3 = wht5(a3, lane);
    a4 = wht5(a4, lane);
    a5 = wht5(a5, lane);
    a6 = wht5(a6, lane);

    float* o = out + e * NQ;
    if (lane == 17) o[0] = a0;                 // q0: L={4,0}
    if (lane == 8)  { o[1] = a1; o[7] = a3; }  // q1: L={3},J=8 ; q7: L={3},J=2
    if (lane == 20) o[2] = a2;                 // q2: L={4,2},J=4
    if (lane == 10) o[3] = a3;                 // q3: L={3,1},J=2
    if (lane == 5)  o[4] = a4;                 // q4: L={2,0},J=1
    if (lane == 2)  { o[5] = a5; o[9] = a6; }  // q5: L={1},J=8,H ; q9: L={1},H
    if (lane == 16) o[6] = a2;                 // q6: L={4},J=4
    if (lane == 4)  o[8] = a4;                 // q8: L={2},J=1
}

extern "C" void kernel_launch(void* const* d_in, const int* in_sizes, int n_in,
                              void* d_out, int out_size) {
    const float* x       = (const float*)d_in[0];  // (16384, 64)
    const float* Wm      = (const float*)d_in[1];  // (10, 64)
    const float* b       = (const float*)d_in[2];  // (10,)
    const float* weights = (const float*)d_in[3];  // (6, 10, 3)
    float* out = (float*)d_out;                    // (16384, 10)

    const int smem_bytes = (11020 + 16) * sizeof(float);
    cudaFuncSetAttribute(qsim_kernel,
                         cudaFuncAttributeMaxDynamicSharedMemorySize, smem_bytes);

    prep_kernel<<<1, 1024>>>(weights);
    qsim_kernel<<<BATCH / 8, 256, smem_bytes>>>(x, Wm, b, out);
}